// round 3
// baseline (speedup 1.0000x reference)
#include <cuda_runtime.h>
#include <cstdint>

#define D        64
#define TILE     128
#define NTHREADS 256

// fma.rn.f32x2 (packed fp32 FMA, sm_100+) is only reachable via PTX.
// Set to 0 if the target ptxas rejects it — fallback is two scalar fmaf
// with bit-identical semantics.
#define USE_F32X2 1

__device__ __forceinline__ unsigned long long pack2(float x, float y) {
    unsigned long long r;
    asm("mov.b64 %0, {%1, %2};" : "=l"(r) : "f"(x), "f"(y));
    return r;
}
__device__ __forceinline__ void unpack2(unsigned long long v, float& x, float& y) {
    asm("mov.b64 {%0, %1}, %2;" : "=f"(x), "=f"(y) : "l"(v));
}
__device__ __forceinline__ unsigned long long fma2(unsigned long long a,
                                                   unsigned long long b,
                                                   unsigned long long c) {
#if USE_F32X2
    unsigned long long d;
    asm("fma.rn.f32x2 %0, %1, %2, %3;" : "=l"(d) : "l"(a), "l"(b), "l"(c));
    return d;
#else
    float ax, ay, bx, by, cx, cy;
    unpack2(a, ax, ay); unpack2(b, bx, by); unpack2(c, cx, cy);
    return pack2(fmaf(ax, bx, cx), fmaf(ay, by, cy));
#endif
}

// One block = 128 edges of ONE relation.
//  1) stage W_r [64x64] in smem (16 KB)
//  2) gather 128 src feature rows into smem A [128x64] (32 KB)
//  3) register-tiled GEMM: 256 thr as 32(row-groups) x 8(col-groups),
//     each thread owns 4 rows x 8 cols (4x4 f32x2 accumulators)
//  4) scatter-add via red.global.add.v4.f32 into out[dst]
__global__ __launch_bounds__(NTHREADS) void rgcn_edge_kernel(
    const float* __restrict__ feat,
    const float* __restrict__ weight,
    const int*   __restrict__ edge_src,
    const int*   __restrict__ edge_dst,
    float*       __restrict__ out,
    int E)
{
    __shared__ float Wsm[D][D];     // 16 KB
    __shared__ float Asm[TILE][D];  // 32 KB  (48 KB static total -> 4 CTAs/SM)

    const int rel = blockIdx.y;
    const int e0  = blockIdx.x * TILE;
    const int tid = threadIdx.x;

    // ---- stage W_r (vectorized, 4 float4 per thread) ----
    {
        const float4* wg = reinterpret_cast<const float4*>(weight + (size_t)rel * D * D);
        float4*       ws = reinterpret_cast<float4*>(&Wsm[0][0]);
        #pragma unroll
        for (int i = 0; i < (D * D / 4) / NTHREADS; ++i)
            ws[tid + i * NTHREADS] = wg[tid + i * NTHREADS];
    }

    // ---- gather src rows: 16 consecutive threads stream one 256B row ----
    // 8 independent LDG.128 per thread -> MLP ~8, L2 latency well covered.
    {
        const int* srcp = edge_src + (size_t)rel * E;
        #pragma unroll
        for (int j = 0; j < (TILE * D / 4) / NTHREADS; ++j) {
            int ldx = tid + j * NTHREADS;
            int e   = ldx >> 4;    // edge within tile
            int c4  = ldx & 15;    // float4 within row
            int eg  = e0 + e;
            float4 v = make_float4(0.f, 0.f, 0.f, 0.f);
            if (eg < E) {
                int s = __ldg(srcp + eg);
                v = reinterpret_cast<const float4*>(feat + (size_t)s * D)[c4];
            }
            reinterpret_cast<float4*>(&Asm[e][0])[c4] = v;
        }
    }
    __syncthreads();

    // ---- GEMM: C[128][64] = A[128][64] x W[64][64] ----
    const int tc = tid & 7;    // col group: cols [8*tc, 8*tc+8)
    const int tr = tid >> 3;   // row group: rows [4*tr, 4*tr+4)

    unsigned long long acc[4][4];
    #pragma unroll
    for (int i = 0; i < 4; ++i)
        #pragma unroll
        for (int p = 0; p < 4; ++p)
            acc[i][p] = 0ULL;   // bit pattern of (0.0f, 0.0f)

    #pragma unroll
    for (int k = 0; k < D; k += 4) {
        float4 a4[4];
        #pragma unroll
        for (int i = 0; i < 4; ++i)
            a4[i] = *reinterpret_cast<const float4*>(&Asm[4 * tr + i][k]);

        #pragma unroll
        for (int kk = 0; kk < 4; ++kk) {
            // 8 distinct 16B addrs per warp within one W row: conflict-free
            ulonglong2 b0 = *reinterpret_cast<const ulonglong2*>(&Wsm[k + kk][8 * tc]);
            ulonglong2 b1 = *reinterpret_cast<const ulonglong2*>(&Wsm[k + kk][8 * tc + 4]);
            #pragma unroll
            for (int i = 0; i < 4; ++i) {
                float av = (kk == 0) ? a4[i].x : (kk == 1) ? a4[i].y
                         : (kk == 2) ? a4[i].z : a4[i].w;
                unsigned long long aa = pack2(av, av);
                acc[i][0] = fma2(aa, b0.x, acc[i][0]);
                acc[i][1] = fma2(aa, b0.y, acc[i][1]);
                acc[i][2] = fma2(aa, b1.x, acc[i][2]);
                acc[i][3] = fma2(aa, b1.y, acc[i][3]);
            }
        }
    }

    // ---- scatter-add into out[dst]: 2x red.global.add.v4 per edge-slice ----
    {
        const int* dstp = edge_dst + (size_t)rel * E;
        #pragma unroll
        for (int i = 0; i < 4; ++i) {
            int eg = e0 + 4 * tr + i;
            if (eg < E) {
                int    dn = __ldg(dstp + eg);
                float* op = out + (size_t)dn * D + 8 * tc;   // 32B aligned
                float x0, x1, x2, x3;
                unpack2(acc[i][0], x0, x1);
                unpack2(acc[i][1], x2, x3);
                asm volatile("red.global.add.v4.f32 [%0], {%1,%2,%3,%4};"
                             :: "l"(op), "f"(x0), "f"(x1), "f"(x2), "f"(x3) : "memory");
                unpack2(acc[i][2], x0, x1);
                unpack2(acc[i][3], x2, x3);
                asm volatile("red.global.add.v4.f32 [%0], {%1,%2,%3,%4};"
                             :: "l"(op + 4), "f"(x0), "f"(x1), "f"(x2), "f"(x3) : "memory");
            }
        }
    }
}

extern "C" void kernel_launch(void* const* d_in, const int* in_sizes, int n_in,
                              void* d_out, int out_size)
{
    const float* feat     = (const float*)d_in[0];
    const float* weight   = (const float*)d_in[1];
    const int*   edge_src = (const int*)d_in[2];
    const int*   edge_dst = (const int*)d_in[3];
    float*       out      = (float*)d_out;

    const int R = in_sizes[1] / (D * D);   // 8
    const int E = in_sizes[2] / R;         // 100000

    // out is poisoned to 0xAA before timing; we accumulate, so zero it first.
    // (async memset is graph-capturable as a memset node)
    cudaMemsetAsync(d_out, 0, (size_t)out_size * sizeof(float));

    dim3 grid((E + TILE - 1) / TILE, R);
    rgcn_edge_kernel<<<grid, NTHREADS>>>(feat, weight, edge_src, edge_dst, out, E);
}

// round 6
// speedup vs baseline: 2.0441x; 2.0441x over previous
#include <cuda_runtime.h>
#include <cuda_bf16.h>
#include <cstdint>

#define D         64
#define TILE      128      // edges per CTA (= GEMM M)
#define NTHREADS  256
#define CAP_N     100000
#define CAP_R     8

// ---------------- device scratch (no allocs allowed) ----------------
__device__ __nv_bfloat16 g_feat_hi[CAP_N * D];
__device__ __nv_bfloat16 g_feat_lo[CAP_N * D];
__device__ __nv_bfloat16 g_wt_hi[CAP_R * D * D];   // W^T: [r][n][k]
__device__ __nv_bfloat16 g_wt_lo[CAP_R * D * D];

// ---------------- helpers ----------------
__device__ __forceinline__ uint32_t smem_u32(const void* p) {
    uint32_t a;
    asm("{ .reg .u64 t; cvta.to.shared.u64 t, %1; cvt.u32.u64 %0, t; }" : "=r"(a) : "l"(p));
    return a;
}
__device__ __forceinline__ uint32_t sw128(uint32_t off) { return off ^ ((off >> 3) & 0x70); }

__device__ __forceinline__ void ldsm_x4(uint32_t* r, uint32_t addr) {
    asm volatile("ldmatrix.sync.aligned.m8n8.x4.shared.b16 {%0,%1,%2,%3}, [%4];"
                 : "=r"(r[0]), "=r"(r[1]), "=r"(r[2]), "=r"(r[3]) : "r"(addr));
}
__device__ __forceinline__ void ldsm_x2(uint32_t* r, uint32_t addr) {
    asm volatile("ldmatrix.sync.aligned.m8n8.x2.shared.b16 {%0,%1}, [%2];"
                 : "=r"(r[0]), "=r"(r[1]) : "r"(addr));
}
__device__ __forceinline__ void mma_bf16(float* d, const uint32_t* a, const uint32_t* b) {
    asm volatile("mma.sync.aligned.m16n8k16.row.col.f32.bf16.bf16.f32 "
                 "{%0,%1,%2,%3}, {%4,%5,%6,%7}, {%8,%9}, {%0,%1,%2,%3};"
                 : "+f"(d[0]), "+f"(d[1]), "+f"(d[2]), "+f"(d[3])
                 : "r"(a[0]), "r"(a[1]), "r"(a[2]), "r"(a[3]), "r"(b[0]), "r"(b[1]));
}

// ---------------- pre-kernels: split-precision decompose ----------------
__global__ void decompose_feat_kernel(const float* __restrict__ feat, int nelem) {
    int i = blockIdx.x * blockDim.x + threadIdx.x;  // one float4 / thread
    if (i * 4 >= nelem) return;
    float4 v = reinterpret_cast<const float4*>(feat)[i];
    __nv_bfloat16 h0 = __float2bfloat16(v.x), h1 = __float2bfloat16(v.y);
    __nv_bfloat16 h2 = __float2bfloat16(v.z), h3 = __float2bfloat16(v.w);
    __nv_bfloat162 hh0 = __nv_bfloat162(h0, h1), hh1 = __nv_bfloat162(h2, h3);
    __nv_bfloat162 ll0 = __nv_bfloat162(__float2bfloat16(v.x - __bfloat162float(h0)),
                                        __float2bfloat16(v.y - __bfloat162float(h1)));
    __nv_bfloat162 ll1 = __nv_bfloat162(__float2bfloat16(v.z - __bfloat162float(h2)),
                                        __float2bfloat16(v.w - __bfloat162float(h3)));
    reinterpret_cast<__nv_bfloat162*>(g_feat_hi)[i * 2]     = hh0;
    reinterpret_cast<__nv_bfloat162*>(g_feat_hi)[i * 2 + 1] = hh1;
    reinterpret_cast<__nv_bfloat162*>(g_feat_lo)[i * 2]     = ll0;
    reinterpret_cast<__nv_bfloat162*>(g_feat_lo)[i * 2 + 1] = ll1;
}

__global__ void decompose_weight_kernel(const float* __restrict__ weight, int R) {
    int i = blockIdx.x * blockDim.x + threadIdx.x;  // over R*D*D, as [r][n][k]
    if (i >= R * D * D) return;
    int k = i % D, n = (i / D) % D, r = i / (D * D);
    float x = weight[(r * D + k) * D + n];          // transpose: W[k][n] -> Wt[n][k]
    __nv_bfloat16 h = __float2bfloat16(x);
    g_wt_hi[i] = h;
    g_wt_lo[i] = __float2bfloat16(x - __bfloat162float(h));
}

// ---------------- main fused kernel ----------------
// dyn smem (49152 B):
//   [0,     16384): Ah  128 rows x 128B (64 bf16) SW128
//   [16384, 32768): Al
//   [32768, 40960): Bh = Wt_hi  64 rows x 128B
//   [40960, 49152): Bl = Wt_lo
// After MMA, region [0, 34816) is reused as D [128][68] fp32 (padded stride).
#define SM_AH   0
#define SM_AL   16384
#define SM_BH   32768
#define SM_BL   40960
#define SM_BYTES 49152
#define DSTRIDE 68

__global__ __launch_bounds__(NTHREADS, 2) void rgcn_hmma_kernel(
    const int* __restrict__ edge_src,
    const int* __restrict__ edge_dst,
    float*     __restrict__ out,
    int E)
{
    extern __shared__ char smem[];
    const uint32_t sb  = smem_u32(smem);
    const int tid  = threadIdx.x;
    const int lane = tid & 31;
    const int wid  = tid >> 5;
    const int rel  = blockIdx.y;
    const int e0   = blockIdx.x * TILE;
    const int wm   = wid & 3;    // M group: rows [32*wm, +32)
    const int wn   = wid >> 2;   // N group: cols [32*wn, +32)

    // ---- stage B tiles: Wt hi/lo (64 rows x 8 x 16B chunks, sw128) ----
    {
        const __nv_bfloat16* wh = g_wt_hi + (size_t)rel * D * D;
        const __nv_bfloat16* wl = g_wt_lo + (size_t)rel * D * D;
        #pragma unroll
        for (int j = 0; j < 4; ++j) {
            int ldx = tid + j * NTHREADS;
            int t   = ldx >> 9;          // 0 = hi, 1 = lo
            int n   = (ldx >> 3) & 63;
            int c   = ldx & 7;
            uint4 v = reinterpret_cast<const uint4*>((t ? wl : wh) + n * D)[c];
            uint32_t off = sw128(n * 128 + c * 16);
            *reinterpret_cast<uint4*>(smem + (t ? SM_BL : SM_BH) + off) = v;
        }
    }

    // ---- gather A tiles: 128 edges x hi/lo rows (16B chunks, sw128) ----
    {
        const int* srcp = edge_src + (size_t)rel * E;
        #pragma unroll
        for (int j = 0; j < 4; ++j) {
            int ldx = tid + j * NTHREADS;   // edge(7b) x chunk(3b)
            int e   = ldx >> 3;
            int c   = ldx & 7;
            int eg  = e0 + e;
            uint4 vh = make_uint4(0, 0, 0, 0), vl = vh;
            if (eg < E) {
                int s = __ldg(srcp + eg);
                vh = reinterpret_cast<const uint4*>(g_feat_hi + (size_t)s * D)[c];
                vl = reinterpret_cast<const uint4*>(g_feat_lo + (size_t)s * D)[c];
            }
            uint32_t off = sw128(e * 128 + c * 16);
            *reinterpret_cast<uint4*>(smem + SM_AH + off) = vh;
            *reinterpret_cast<uint4*>(smem + SM_AL + off) = vl;
        }
    }
    __syncthreads();

    // ---- HMMA: warp computes 32x32; 3 passes AhBh + AhBl + AlBh ----
    float d[2][4][4];
    #pragma unroll
    for (int mt = 0; mt < 2; ++mt)
        #pragma unroll
        for (int nt = 0; nt < 4; ++nt)
            #pragma unroll
            for (int q = 0; q < 4; ++q) d[mt][nt][q] = 0.f;

    const int ra = lane & 15;                 // A row within m16 tile
    const int ca = (lane >> 4) * 16;          // A k-chunk byte offset (x4)
    const int rb = lane & 7;                  // B row within n8 tile
    const int cb = ((lane >> 3) & 1) * 16;    // B k-chunk byte offset (x2)

    #pragma unroll
    for (int ks = 0; ks < 4; ++ks) {
        const uint32_t kbase = ks * 32;       // 16 bf16 = 32 B per k-step
        uint32_t bh[4][2], bl[4][2];
        #pragma unroll
        for (int nt = 0; nt < 4; ++nt) {
            uint32_t off = (wn * 32 + nt * 8 + rb) * 128 + kbase + cb;
            ldsm_x2(bh[nt], sb + SM_BH + sw128(off));
            ldsm_x2(bl[nt], sb + SM_BL + sw128(off));
        }
        #pragma unroll
        for (int mt = 0; mt < 2; ++mt) {
            uint32_t offa = (wm * 32 + mt * 16 + ra) * 128 + kbase + ca;
            uint32_t ah[4], al[4];
            ldsm_x4(ah, sb + SM_AH + sw128(offa));
            ldsm_x4(al, sb + SM_AL + sw128(offa));
            #pragma unroll
            for (int nt = 0; nt < 4; ++nt) {
                mma_bf16(d[mt][nt], ah, bh[nt]);
                mma_bf16(d[mt][nt], ah, bl[nt]);
                mma_bf16(d[mt][nt], al, bh[nt]);
            }
        }
    }
    __syncthreads();   // all ldmatrix reads done before overlaying D

    // ---- D -> smem (padded stride 68 floats) ----
    float* smD = reinterpret_cast<float*>(smem);
    {
        const int t4 = lane >> 2;             // row-in-8
        const int t2 = (lane & 3) * 2;        // col pair
        #pragma unroll
        for (int mt = 0; mt < 2; ++mt) {
            int r0 = wm * 32 + mt * 16 + t4;
            #pragma unroll
            for (int nt = 0; nt < 4; ++nt) {
                int c = wn * 32 + nt * 8 + t2;
                *reinterpret_cast<float2*>(smD + r0 * DSTRIDE + c) =
                    make_float2(d[mt][nt][0], d[mt][nt][1]);
                *reinterpret_cast<float2*>(smD + (r0 + 8) * DSTRIDE + c) =
                    make_float2(d[mt][nt][2], d[mt][nt][3]);
            }
        }
    }
    __syncthreads();

    // ---- coalesced scatter: 16 threads per edge row, red.global.add.v4 ----
    {
        const int* dstp = edge_dst + (size_t)rel * E;
        const int c4 = tid & 15;
        #pragma unroll
        for (int it = 0; it < 8; ++it) {
            int row = it * 16 + (tid >> 4);
            int eg  = e0 + row;
            if (eg < E) {
                float4 v = *reinterpret_cast<const float4*>(smD + row * DSTRIDE + c4 * 4);
                int    dn = __ldg(dstp + eg);
                float* op = out + (size_t)dn * D + c4 * 4;
                asm volatile("red.global.add.v4.f32 [%0], {%1,%2,%3,%4};"
                             :: "l"(op), "f"(v.x), "f"(v.y), "f"(v.z), "f"(v.w) : "memory");
            }
        }
    }
}

// ---------------- launch ----------------
extern "C" void kernel_launch(void* const* d_in, const int* in_sizes, int n_in,
                              void* d_out, int out_size)
{
    const float* feat     = (const float*)d_in[0];
    const float* weight   = (const float*)d_in[1];
    const int*   edge_src = (const int*)d_in[2];
    const int*   edge_dst = (const int*)d_in[3];
    float*       out      = (float*)d_out;

    const int nelem = in_sizes[0];            // N * 64
    const int R     = in_sizes[1] / (D * D);  // 8
    const int E     = in_sizes[2] / R;        // 100000

    cudaFuncSetAttribute(rgcn_hmma_kernel,
                         cudaFuncAttributeMaxDynamicSharedMemorySize, SM_BYTES);

    cudaMemsetAsync(d_out, 0, (size_t)out_size * sizeof(float));
    decompose_feat_kernel<<<(nelem / 4 + 255) / 256, 256>>>(feat, nelem);
    decompose_weight_kernel<<<(R * D * D + 255) / 256, 256>>>(weight, R);

    dim3 grid((E + TILE - 1) / TILE, R);
    rgcn_hmma_kernel<<<grid, NTHREADS, SM_BYTES>>>(edge_src, edge_dst, out, E);
}

// round 7
// speedup vs baseline: 2.3079x; 1.1290x over previous
#include <cuda_runtime.h>
#include <cuda_bf16.h>
#include <cstdint>

#define D         64
#define TILE      256      // edges per CTA (= GEMM M)
#define NTHREADS  256
#define CAP_R     8

// ---------------- device scratch (no allocs allowed) ----------------
__device__ __nv_bfloat16 g_wt_hi[CAP_R * D * D];   // W^T: [r][n][k]
__device__ __nv_bfloat16 g_wt_lo[CAP_R * D * D];

// ---------------- helpers ----------------
__device__ __forceinline__ uint32_t smem_u32(const void* p) {
    uint32_t a;
    asm("{ .reg .u64 t; cvta.to.shared.u64 t, %1; cvt.u32.u64 %0, t; }" : "=r"(a) : "l"(p));
    return a;
}
__device__ __forceinline__ uint32_t sw128(uint32_t off) { return off ^ ((off >> 3) & 0x70); }

__device__ __forceinline__ void ldsm_x4(uint32_t* r, uint32_t addr) {
    asm volatile("ldmatrix.sync.aligned.m8n8.x4.shared.b16 {%0,%1,%2,%3}, [%4];"
                 : "=r"(r[0]), "=r"(r[1]), "=r"(r[2]), "=r"(r[3]) : "r"(addr));
}
__device__ __forceinline__ void ldsm_x2(uint32_t* r, uint32_t addr) {
    asm volatile("ldmatrix.sync.aligned.m8n8.x2.shared.b16 {%0,%1}, [%2];"
                 : "=r"(r[0]), "=r"(r[1]) : "r"(addr));
}
__device__ __forceinline__ void mma_bf16(float* d, const uint32_t* a, const uint32_t* b) {
    asm volatile("mma.sync.aligned.m16n8k16.row.col.f32.bf16.bf16.f32 "
                 "{%0,%1,%2,%3}, {%4,%5,%6,%7}, {%8,%9}, {%0,%1,%2,%3};"
                 : "+f"(d[0]), "+f"(d[1]), "+f"(d[2]), "+f"(d[3])
                 : "r"(a[0]), "r"(a[1]), "r"(a[2]), "r"(a[3]), "r"(b[0]), "r"(b[1]));
}
__device__ __forceinline__ uint32_t bfpack(float x, float y) {
    __nv_bfloat162 t = __floats2bfloat162_rn(x, y);
    return *reinterpret_cast<uint32_t*>(&t);
}

// ---------------- pre-kernel: weight transpose + hi/lo decompose ----------------
__global__ void decompose_weight_kernel(const float* __restrict__ weight, int R) {
    int i = blockIdx.x * blockDim.x + threadIdx.x;  // over R*D*D, as [r][n][k]
    if (i >= R * D * D) return;
    int k = i % D, n = (i / D) % D, r = i / (D * D);
    float x = weight[(r * D + k) * D + n];          // transpose: W[k][n] -> Wt[n][k]
    __nv_bfloat16 h = __float2bfloat16(x);
    g_wt_hi[i] = h;
    g_wt_lo[i] = __float2bfloat16(x - __bfloat162float(h));
}

// ---------------- main fused kernel ----------------
// dyn smem (81920 B):
//   [0,     32768): Ah  256 rows x 128B (64 bf16) SW128
//   [32768, 65536): Al
//   [65536, 73728): Bh = Wt_hi  64 rows x 128B
//   [73728, 81920): Bl = Wt_lo
// After MMA, [0, 69632) reused as D [256][68] fp32 (padded stride).
#define SM_AH    0
#define SM_AL    32768
#define SM_BH    65536
#define SM_BL    73728
#define SM_BYTES 81920
#define DSTRIDE  68

__global__ __launch_bounds__(NTHREADS, 2) void rgcn_hmma_kernel(
    const float* __restrict__ feat,
    const int*   __restrict__ edge_src,
    const int*   __restrict__ edge_dst,
    float*       __restrict__ out,
    int E)
{
    extern __shared__ char smem[];
    const uint32_t sb  = smem_u32(smem);
    const int tid  = threadIdx.x;
    const int lane = tid & 31;
    const int wid  = tid >> 5;   // 8 warps; warp w owns rows [32w, 32w+32)
    const int rel  = blockIdx.y;
    const int e0   = blockIdx.x * TILE;

    // ---- stage B tiles: Wt hi/lo (64 rows x 8 x 16B chunks, sw128) ----
    {
        const __nv_bfloat16* wh = g_wt_hi + (size_t)rel * D * D;
        const __nv_bfloat16* wl = g_wt_lo + (size_t)rel * D * D;
        #pragma unroll
        for (int j = 0; j < 4; ++j) {
            int ldx = tid + j * NTHREADS;   // 1024 slots
            int t   = ldx >> 9;             // 0 = hi, 1 = lo
            int n   = (ldx >> 3) & 63;
            int c   = ldx & 7;
            uint4 v = reinterpret_cast<const uint4*>((t ? wl : wh) + n * D)[c];
            uint32_t off = sw128(n * 128 + c * 16);
            *reinterpret_cast<uint4*>(smem + (t ? SM_BL : SM_BH) + off) = v;
        }
    }

    // ---- gather fp32 rows + in-register hi/lo decompose -> smem bf16 tiles ----
    // slot = edge(8b) x chunk(3b); chunk c covers fp32 bytes [32c, 32c+32)
    {
        const int* srcp = edge_src + (size_t)rel * E;
        #pragma unroll
        for (int j = 0; j < 8; ++j) {
            int slot = tid + j * NTHREADS;   // 2048 slots
            int e    = slot >> 3;
            int c    = slot & 7;
            int eg   = e0 + e;
            float4 v0 = make_float4(0.f, 0.f, 0.f, 0.f), v1 = v0;
            if (eg < E) {
                int s = __ldg(srcp + eg);
                const float4* fp = reinterpret_cast<const float4*>(feat + (size_t)s * D) + c * 2;
                v0 = fp[0];
                v1 = fp[1];
            }
            float f[8] = {v0.x, v0.y, v0.z, v0.w, v1.x, v1.y, v1.z, v1.w};
            float h[8], l[8];
            #pragma unroll
            for (int q = 0; q < 8; ++q) {
                h[q] = __bfloat162float(__float2bfloat16(f[q]));
                l[q] = f[q] - h[q];
            }
            uint4 hv = make_uint4(bfpack(h[0], h[1]), bfpack(h[2], h[3]),
                                  bfpack(h[4], h[5]), bfpack(h[6], h[7]));
            uint4 lv = make_uint4(bfpack(l[0], l[1]), bfpack(l[2], l[3]),
                                  bfpack(l[4], l[5]), bfpack(l[6], l[7]));
            uint32_t off = sw128(e * 128 + c * 16);
            *reinterpret_cast<uint4*>(smem + SM_AH + off) = hv;
            *reinterpret_cast<uint4*>(smem + SM_AL + off) = lv;
        }
    }
    __syncthreads();

    // ---- HMMA: each warp computes 32 rows x 64 cols; AhBh + AhBl + AlBh ----
    float d[2][8][4];
    #pragma unroll
    for (int mt = 0; mt < 2; ++mt)
        #pragma unroll
        for (int nt = 0; nt < 8; ++nt)
            #pragma unroll
            for (int q = 0; q < 4; ++q) d[mt][nt][q] = 0.f;

    const int ra = lane & 15;                 // A row within m16 tile
    const int ca = (lane >> 4) * 16;          // A k-chunk byte offset (x4)
    const int rb = lane & 7;                  // B row within n8 tile
    const int cb = ((lane >> 3) & 1) * 16;    // B k-chunk byte offset (x2)

    #pragma unroll
    for (int ks = 0; ks < 4; ++ks) {
        const uint32_t kbase = ks * 32;       // 16 bf16 = 32B per k-step
        uint32_t ah0[4], al0[4], ah1[4], al1[4];
        {
            uint32_t o0 = (wid * 32 + ra) * 128 + kbase + ca;
            uint32_t o1 = (wid * 32 + 16 + ra) * 128 + kbase + ca;
            ldsm_x4(ah0, sb + SM_AH + sw128(o0));
            ldsm_x4(al0, sb + SM_AL + sw128(o0));
            ldsm_x4(ah1, sb + SM_AH + sw128(o1));
            ldsm_x4(al1, sb + SM_AL + sw128(o1));
        }
        #pragma unroll
        for (int nt = 0; nt < 8; ++nt) {
            uint32_t bh[2], bl[2];
            uint32_t ob = (nt * 8 + rb) * 128 + kbase + cb;
            ldsm_x2(bh, sb + SM_BH + sw128(ob));
            ldsm_x2(bl, sb + SM_BL + sw128(ob));
            mma_bf16(d[0][nt], ah0, bh);
            mma_bf16(d[0][nt], ah0, bl);
            mma_bf16(d[0][nt], al0, bh);
            mma_bf16(d[1][nt], ah1, bh);
            mma_bf16(d[1][nt], ah1, bl);
            mma_bf16(d[1][nt], al1, bh);
        }
    }
    __syncthreads();   // all ldmatrix reads done before overlaying D

    // ---- D -> smem (padded stride 68 floats) ----
    float* smD = reinterpret_cast<float*>(smem);
    {
        const int t4 = lane >> 2;             // row-in-8
        const int t2 = (lane & 3) * 2;        // col pair
        #pragma unroll
        for (int mt = 0; mt < 2; ++mt) {
            int r0 = wid * 32 + mt * 16 + t4;
            #pragma unroll
            for (int nt = 0; nt < 8; ++nt) {
                int c = nt * 8 + t2;
                *reinterpret_cast<float2*>(smD + r0 * DSTRIDE + c) =
                    make_float2(d[mt][nt][0], d[mt][nt][1]);
                *reinterpret_cast<float2*>(smD + (r0 + 8) * DSTRIDE + c) =
                    make_float2(d[mt][nt][2], d[mt][nt][3]);
            }
        }
    }
    __syncthreads();

    // ---- coalesced scatter: 16 threads per edge row, red.global.add.v4 ----
    {
        const int* dstp = edge_dst + (size_t)rel * E;
        const int c4 = tid & 15;
        #pragma unroll
        for (int it = 0; it < 16; ++it) {
            int row = it * 16 + (tid >> 4);
            int eg  = e0 + row;
            if (eg < E) {
                float4 v = *reinterpret_cast<const float4*>(smD + row * DSTRIDE + c4 * 4);
                int    dn = __ldg(dstp + eg);
                float* op = out + (size_t)dn * D + c4 * 4;
                asm volatile("red.global.add.v4.f32 [%0], {%1,%2,%3,%4};"
                             :: "l"(op), "f"(v.x), "f"(v.y), "f"(v.z), "f"(v.w) : "memory");
            }
        }
    }
}

// ---------------- launch ----------------
extern "C" void kernel_launch(void* const* d_in, const int* in_sizes, int n_in,
                              void* d_out, int out_size)
{
    const float* feat     = (const float*)d_in[0];
    const float* weight   = (const float*)d_in[1];
    const int*   edge_src = (const int*)d_in[2];
    const int*   edge_dst = (const int*)d_in[3];
    float*       out      = (float*)d_out;

    const int R = in_sizes[1] / (D * D);  // 8
    const int E = in_sizes[2] / R;        // 100000

    cudaFuncSetAttribute(rgcn_hmma_kernel,
                         cudaFuncAttributeMaxDynamicSharedMemorySize, SM_BYTES);

    cudaMemsetAsync(d_out, 0, (size_t)out_size * sizeof(float));
    decompose_weight_kernel<<<(R * D * D + 255) / 256, 256>>>(weight, R);

    dim3 grid((E + TILE - 1) / TILE, R);
    rgcn_hmma_kernel<<<grid, NTHREADS, SM_BYTES>>>(feat, edge_src, edge_dst, out, E);
}

// round 8
// speedup vs baseline: 2.5873x; 1.1211x over previous
#include <cuda_runtime.h>
#include <cuda_bf16.h>
#include <cstdint>

#define D         64
#define TILE      128      // edges per CTA (= GEMM M)
#define NTHREADS  256
#define CAP_R     8

// ---------------- device scratch (no allocs allowed) ----------------
__device__ __nv_bfloat16 g_wt_hi[CAP_R * D * D];   // W^T: [r][n][k]
__device__ __nv_bfloat16 g_wt_lo[CAP_R * D * D];

// ---------------- helpers ----------------
__device__ __forceinline__ uint32_t smem_u32(const void* p) {
    uint32_t a;
    asm("{ .reg .u64 t; cvta.to.shared.u64 t, %1; cvt.u32.u64 %0, t; }" : "=r"(a) : "l"(p));
    return a;
}
__device__ __forceinline__ uint32_t sw128(uint32_t off) { return off ^ ((off >> 3) & 0x70); }

__device__ __forceinline__ void ldsm_x4(uint32_t* r, uint32_t addr) {
    asm volatile("ldmatrix.sync.aligned.m8n8.x4.shared.b16 {%0,%1,%2,%3}, [%4];"
                 : "=r"(r[0]), "=r"(r[1]), "=r"(r[2]), "=r"(r[3]) : "r"(addr));
}
__device__ __forceinline__ void mma_bf16(float* d, const uint32_t* a, const uint32_t* b) {
    asm volatile("mma.sync.aligned.m16n8k16.row.col.f32.bf16.bf16.f32 "
                 "{%0,%1,%2,%3}, {%4,%5,%6,%7}, {%8,%9}, {%0,%1,%2,%3};"
                 : "+f"(d[0]), "+f"(d[1]), "+f"(d[2]), "+f"(d[3])
                 : "r"(a[0]), "r"(a[1]), "r"(a[2]), "r"(a[3]), "r"(b[0]), "r"(b[1]));
}
__device__ __forceinline__ uint32_t bfpack(float x, float y) {
    __nv_bfloat162 t = __floats2bfloat162_rn(x, y);
    return *reinterpret_cast<uint32_t*>(&t);
}

// ---------------- pre-kernel: weight transpose + hi/lo decompose ----------------
__global__ void decompose_weight_kernel(const float* __restrict__ weight, int R) {
    int i = blockIdx.x * blockDim.x + threadIdx.x;  // over R*D*D, as [r][n][k]
    if (i >= R * D * D) return;
    int k = i % D, n = (i / D) % D, r = i / (D * D);
    float x = weight[(r * D + k) * D + n];          // transpose: W[k][n] -> Wt[n][k]
    __nv_bfloat16 h = __float2bfloat16(x);
    g_wt_hi[i] = h;
    g_wt_lo[i] = __float2bfloat16(x - __bfloat162float(h));
}

// ---------------- main fused kernel ----------------
// dyn smem (49152 B):
//   [0,     16384): Ah  128 rows x 128B (64 bf16) SW128
//   [16384, 32768): Al
//   [32768, 40960): Bh = Wt_hi  64 rows x 128B
//   [40960, 49152): Bl = Wt_lo
// After MMA, [0, 34816) reused as D [128][68] fp32 (padded stride).
#define SM_AH    0
#define SM_AL    16384
#define SM_BH    32768
#define SM_BL    40960
#define SM_BYTES 49152
#define DSTRIDE  68

__global__ __launch_bounds__(NTHREADS, 3) void rgcn_hmma_kernel(
    const float* __restrict__ feat,
    const int*   __restrict__ edge_src,
    const int*   __restrict__ edge_dst,
    float*       __restrict__ out,
    int E)
{
    extern __shared__ char smem[];
    const uint32_t sb  = smem_u32(smem);
    const int tid  = threadIdx.x;
    const int lane = tid & 31;
    const int wid  = tid >> 5;   // 8 warps; warp w owns rows [16w, 16w+16)
    const int rel  = blockIdx.y;
    const int e0   = blockIdx.x * TILE;

    // ---- stage B tiles: Wt hi/lo (64 rows x 8 x 16B chunks, sw128) ----
    {
        const __nv_bfloat16* wh = g_wt_hi + (size_t)rel * D * D;
        const __nv_bfloat16* wl = g_wt_lo + (size_t)rel * D * D;
        #pragma unroll
        for (int j = 0; j < 4; ++j) {
            int ldx = tid + j * NTHREADS;   // 1024 slots
            int t   = ldx >> 9;             // 0 = hi, 1 = lo
            int n   = (ldx >> 3) & 63;
            int c   = ldx & 7;
            uint4 v = reinterpret_cast<const uint4*>((t ? wl : wh) + n * D)[c];
            uint32_t off = sw128(n * 128 + c * 16);
            *reinterpret_cast<uint4*>(smem + (t ? SM_BL : SM_BH) + off) = v;
        }
    }

    // ---- gather fp32 rows + in-register hi/lo decompose -> smem bf16 tiles ----
    // slot = edge(7b) x chunk(3b); chunk c covers fp32 bytes [32c, 32c+32)
    {
        const int* srcp = edge_src + (size_t)rel * E;
        #pragma unroll
        for (int j = 0; j < 4; ++j) {
            int slot = tid + j * NTHREADS;   // 1024 slots
            int e    = slot >> 3;
            int c    = slot & 7;
            int eg   = e0 + e;
            float4 v0 = make_float4(0.f, 0.f, 0.f, 0.f), v1 = v0;
            if (eg < E) {
                int s = __ldg(srcp + eg);
                const float4* fp = reinterpret_cast<const float4*>(feat + (size_t)s * D) + c * 2;
                v0 = fp[0];
                v1 = fp[1];
            }
            float f[8] = {v0.x, v0.y, v0.z, v0.w, v1.x, v1.y, v1.z, v1.w};
            float h[8], l[8];
            #pragma unroll
            for (int q = 0; q < 8; ++q) {
                h[q] = __bfloat162float(__float2bfloat16(f[q]));
                l[q] = f[q] - h[q];
            }
            uint4 hv = make_uint4(bfpack(h[0], h[1]), bfpack(h[2], h[3]),
                                  bfpack(h[4], h[5]), bfpack(h[6], h[7]));
            uint4 lv = make_uint4(bfpack(l[0], l[1]), bfpack(l[2], l[3]),
                                  bfpack(l[4], l[5]), bfpack(l[6], l[7]));
            uint32_t off = sw128(e * 128 + c * 16);
            *reinterpret_cast<uint4*>(smem + SM_AH + off) = hv;
            *reinterpret_cast<uint4*>(smem + SM_AL + off) = lv;
        }
    }
    __syncthreads();

    // ---- HMMA: each warp computes 16 rows x 64 cols; AhBh + AhBl + AlBh ----
    float d[8][4];
    #pragma unroll
    for (int nt = 0; nt < 8; ++nt)
        #pragma unroll
        for (int q = 0; q < 4; ++q) d[nt][q] = 0.f;

    const int ra = lane & 15;                 // A row within m16 tile
    const int ca = (lane >> 4) * 16;          // A k-chunk byte offset (x4)
    // B x4 addressing: lanes 0-7 -> (nt, k-lo), 8-15 -> (nt, k-hi),
    //                  16-23 -> (nt+1, k-lo), 24-31 -> (nt+1, k-hi)
    const int rbp = ((lane >> 4) & 1) * 8 + (lane & 7);  // row within n16 pair
    const int cbp = ((lane >> 3) & 1) * 16;

    #pragma unroll
    for (int ks = 0; ks < 4; ++ks) {
        const uint32_t kbase = ks * 32;       // 16 bf16 = 32B per k-step
        uint32_t ah[4], al[4];
        {
            uint32_t o = (wid * 16 + ra) * 128 + kbase + ca;
            ldsm_x4(ah, sb + SM_AH + sw128(o));
            ldsm_x4(al, sb + SM_AL + sw128(o));
        }
        #pragma unroll
        for (int np = 0; np < 4; ++np) {      // n16 pairs: cols [16np, 16np+16)
            uint32_t bh[4], bl[4];
            uint32_t ob = (np * 16 + rbp) * 128 + kbase + cbp;
            ldsm_x4(bh, sb + SM_BH + sw128(ob));
            ldsm_x4(bl, sb + SM_BL + sw128(ob));
            mma_bf16(d[2 * np],     ah, bh);
            mma_bf16(d[2 * np],     ah, bl);
            mma_bf16(d[2 * np],     al, bh);
            mma_bf16(d[2 * np + 1], ah, bh + 2);
            mma_bf16(d[2 * np + 1], ah, bl + 2);
            mma_bf16(d[2 * np + 1], al, bh + 2);
        }
    }
    __syncthreads();   // all ldmatrix reads done before overlaying D

    // ---- D -> smem (padded stride 68 floats) ----
    float* smD = reinterpret_cast<float*>(smem);
    {
        const int t4 = lane >> 2;             // row-in-8
        const int t2 = (lane & 3) * 2;        // col pair
        int r0 = wid * 16 + t4;
        #pragma unroll
        for (int nt = 0; nt < 8; ++nt) {
            int c = nt * 8 + t2;
            *reinterpret_cast<float2*>(smD + r0 * DSTRIDE + c) =
                make_float2(d[nt][0], d[nt][1]);
            *reinterpret_cast<float2*>(smD + (r0 + 8) * DSTRIDE + c) =
                make_float2(d[nt][2], d[nt][3]);
        }
    }
    __syncthreads();

    // ---- coalesced scatter: 16 threads per edge row, red.global.add.v4 ----
    {
        const int* dstp = edge_dst + (size_t)rel * E;
        const int c4 = tid & 15;
        #pragma unroll
        for (int it = 0; it < 8; ++it) {
            int row = it * 16 + (tid >> 4);
            int eg  = e0 + row;
            if (eg < E) {
                float4 v = *reinterpret_cast<const float4*>(smD + row * DSTRIDE + c4 * 4);
                int    dn = __ldg(dstp + eg);
                float* op = out + (size_t)dn * D + c4 * 4;
                asm volatile("red.global.add.v4.f32 [%0], {%1,%2,%3,%4};"
                             :: "l"(op), "f"(v.x), "f"(v.y), "f"(v.z), "f"(v.w) : "memory");
            }
        }
    }
}

// ---------------- launch ----------------
extern "C" void kernel_launch(void* const* d_in, const int* in_sizes, int n_in,
                              void* d_out, int out_size)
{
    const float* feat     = (const float*)d_in[0];
    const float* weight   = (const float*)d_in[1];
    const int*   edge_src = (const int*)d_in[2];
    const int*   edge_dst = (const int*)d_in[3];
    float*       out      = (float*)d_out;

    const int R = in_sizes[1] / (D * D);  // 8
    const int E = in_sizes[2] / R;        // 100000

    cudaFuncSetAttribute(rgcn_hmma_kernel,
                         cudaFuncAttributeMaxDynamicSharedMemorySize, SM_BYTES);

    cudaMemsetAsync(d_out, 0, (size_t)out_size * sizeof(float));
    decompose_weight_kernel<<<(R * D * D + 255) / 256, 256>>>(weight, R);

    dim3 grid((E + TILE - 1) / TILE, R);
    rgcn_hmma_kernel<<<grid, NTHREADS, SM_BYTES>>>(feat, edge_src, edge_dst, out, E);
}